// round 13
// baseline (speedup 1.0000x reference)
#include <cuda_runtime.h>
#include <cuda_fp16.h>
#include <cstdint>

#define NROWS 32768
#define NFEAT 2048
#define NHID  4096
#define NCLS  512
#define RSX   256            // partial-split factor for column stats

// GEMM tiling: 128x128 CTA tile, BKC=64, 4 warps (2x2), warp tile 64x64
#define BM 128
#define BN 128
#define BKC 64
#define STAGE 32768          // A 16K + B 16K (128B rows, SW128 swizzle)
#define NSTAGE 3
#define SMEM_DYN (NSTAGE * STAGE)

// ---------------- device scratch ----------------
__device__ __half g_xh [(size_t)NROWS * NFEAT];
__device__ __half g_h1 [(size_t)NROWS * NHID];
__device__ __half g_w1h[(size_t)NHID  * NFEAT];
__device__ __half g_w2h[(size_t)NCLS  * NHID];
__device__ float  g_b1f[NHID];
__device__ float  g_b2f[NCLS];
__device__ float  g_scale1[NFEAT], g_shift1[NFEAT];
__device__ float  g_scale2[NHID],  g_shift2[NHID];
__device__ float  g_psum  [(size_t)RSX * NHID];
__device__ float  g_psumsq[(size_t)RSX * NHID];

// ---------------- PTX helpers (family-portable only: sm_80-era) ----------------
__device__ __forceinline__ uint32_t smem_u32(const void* p) {
    uint32_t a;
    asm("{ .reg .u64 t; cvta.to.shared.u64 t, %1; cvt.u32.u64 %0, t; }" : "=r"(a) : "l"(p));
    return a;
}
__device__ __forceinline__ void cp16(uint32_t s, const void* g) {
    asm volatile("cp.async.cg.shared.global [%0], [%1], 16;" :: "r"(s), "l"(g));
}
__device__ __forceinline__ void cp_commit() { asm volatile("cp.async.commit_group;" ::: "memory"); }
__device__ __forceinline__ void cp_wait1()  { asm volatile("cp.async.wait_group 1;" ::: "memory"); }
__device__ __forceinline__ void cp_wait0()  { asm volatile("cp.async.wait_group 0;" ::: "memory"); }

__device__ __forceinline__ void ldsm_x4(uint32_t& d0, uint32_t& d1, uint32_t& d2, uint32_t& d3, uint32_t addr) {
    asm volatile("ldmatrix.sync.aligned.m8n8.x4.shared.b16 {%0,%1,%2,%3}, [%4];"
                 : "=r"(d0), "=r"(d1), "=r"(d2), "=r"(d3) : "r"(addr));
}
__device__ __forceinline__ void mma16816(float* c, const uint32_t* a, uint32_t b0, uint32_t b1) {
    asm volatile("mma.sync.aligned.m16n8k16.row.col.f32.f16.f16.f32 "
                 "{%0,%1,%2,%3}, {%4,%5,%6,%7}, {%8,%9}, {%0,%1,%2,%3};"
                 : "+f"(c[0]), "+f"(c[1]), "+f"(c[2]), "+f"(c[3])
                 : "r"(a[0]), "r"(a[1]), "r"(a[2]), "r"(a[3]), "r"(b0), "r"(b1));
}

// ---------------- stats / conversion kernels (fp32 partials, wide grids) ----------------
// grid (C/1024, RSX); each thread owns 4 consecutive columns over 128 rows.
__global__ __launch_bounds__(256)
void conv_stats_x(const float* __restrict__ X, __half* __restrict__ Xh,
                  int C, int rowsPer) {
    const int c4 = (blockIdx.x * 256 + threadIdx.x) * 4;
    const size_t base = (size_t)blockIdx.y * rowsPer * C + c4;
    float s0 = 0, s1 = 0, s2 = 0, s3 = 0;
    float q0 = 0, q1 = 0, q2 = 0, q3 = 0;
    for (int r = 0; r < rowsPer; r += 4) {
#pragma unroll
        for (int u = 0; u < 4; u++) {
            const size_t o = base + (size_t)(r + u) * C;
            float4 v = *(const float4*)(X + o);
            s0 += v.x; q0 = fmaf(v.x, v.x, q0);
            s1 += v.y; q1 = fmaf(v.y, v.y, q1);
            s2 += v.z; q2 = fmaf(v.z, v.z, q2);
            s3 += v.w; q3 = fmaf(v.w, v.w, q3);
            __half2 hA = __halves2half2(__float2half(v.x), __float2half(v.y));
            __half2 hB = __halves2half2(__float2half(v.z), __float2half(v.w));
            *(uint2*)(Xh + o) = make_uint2(*(uint32_t*)&hA, *(uint32_t*)&hB);
        }
    }
    const int pb = blockIdx.y * C + c4;
    g_psum[pb + 0] = s0; g_psum[pb + 1] = s1; g_psum[pb + 2] = s2; g_psum[pb + 3] = s3;
    g_psumsq[pb + 0] = q0; g_psumsq[pb + 1] = q1; g_psumsq[pb + 2] = q2; g_psumsq[pb + 3] = q3;
}

__global__ void col_stats_finalize(const float* __restrict__ gamma, const float* __restrict__ bnb,
                                   float* __restrict__ scale, float* __restrict__ shift, int C) {
    int c = blockIdx.x * 256 + threadIdx.x;
    double s = 0, q = 0;
    for (int i = 0; i < RSX; i++) { s += (double)g_psum[(size_t)i * C + c]; q += (double)g_psumsq[(size_t)i * C + c]; }
    double mu  = s * (1.0 / NROWS);
    double var = q * (1.0 / NROWS) - mu * mu;
    float a = rsqrtf((float)var + 1e-5f) * gamma[c];
    scale[c] = a;
    shift[c] = bnb[c] - (float)mu * a;
}

__global__ void fold_split(const float* __restrict__ W, const float* __restrict__ bias,
                           const float* __restrict__ scale, const float* __restrict__ shift,
                           __half* __restrict__ Wh, float* __restrict__ bf, int K) {
    int j = blockIdx.x;
    const float* Wr = W + (size_t)j * K;
    float dot = 0.f;
    for (int k = threadIdx.x; k < K; k += 256) {
        float w = Wr[k];
        Wh[(size_t)j * K + k] = __float2half(w * scale[k]);
        dot += w * shift[k];
    }
    __shared__ float red[256];
    red[threadIdx.x] = dot;
    __syncthreads();
    for (int s = 128; s > 0; s >>= 1) {
        if (threadIdx.x < s) red[threadIdx.x] += red[threadIdx.x + s];
        __syncthreads();
    }
    if (threadIdx.x == 0) bf[j] = bias[j] + red[0];
}

// ---------------- mma.sync GEMM: C = A[M,K] @ B[N,K]^T  (fp16, warp tile 64x64) -----------
// 128 threads (4 warps, 2x2). STATS: fused h1 column-stat partials (layer-1 path).
template <bool L2E, bool STATS>
__global__ __launch_bounds__(128, 2)
void gemm_mma(const __half* __restrict__ A, const __half* __restrict__ B,
              const float* __restrict__ bias, const float* __restrict__ Y,
              const float* __restrict__ betap, float* __restrict__ Cout,
              __half* __restrict__ Ch, int K, int Nout) {
    extern __shared__ __align__(1024) char smem[];
    const uint32_t sb = smem_u32(smem);
    const int tid  = threadIdx.x;
    const int wid  = tid >> 5;
    const int lane = tid & 31;
    const int wm   = (wid >> 1) * 64;      // warp m offset in tile
    const int wn   = (wid & 1) * 64;       // warp n offset in tile

    const int ldb = K * 2;  // row stride, bytes
    const char* gA = (const char*)(A + (size_t)(blockIdx.y * BM) * K);
    const char* gB = (const char*)(B + (size_t)(blockIdx.x * BN) * K);
    const int NC = K / BKC;

    // loader: per stage, A = 128x128B + B same; 8 chunks each per thread (128 threads)
    const int lr = tid >> 3;          // 0..15
    const int lc = tid & 7;           // chunk col 0..7
    auto load_stage = [&](int ch, uint32_t s0) {
        size_t kb = (size_t)ch * 128; // 64 halves = 128 bytes
#pragma unroll
        for (int t = 0; t < 8; t++) {
            int r = lr + t * 16;
            uint32_t so = (uint32_t)r * 128 + (uint32_t)((lc ^ (r & 7)) << 4);
            size_t go = (size_t)r * ldb + kb + lc * 16;
            cp16(s0 + so,         gA + go);
            cp16(s0 + 16384 + so, gB + go);
        }
    };

    float acc[4][8][4];
#pragma unroll
    for (int i = 0; i < 4; i++)
#pragma unroll
        for (int j = 0; j < 8; j++)
#pragma unroll
            for (int r = 0; r < 4; r++) acc[i][j][r] = 0.f;

    // hoisted fragment row bases (per-warp invariant)
    const int ar  = wm + (lane & 15);
    const int arx = ar & 7;
    const int br  = wn + (lane & 7) + ((lane & 16) ? 8 : 0);
    const int brx = br & 7;
    const int ahalf = (lane >> 4);
    const int bhalf = ((lane >> 3) & 1);

    // prologue: fill NSTAGE-1 stages
#pragma unroll
    for (int s = 0; s < NSTAGE - 1; s++) { load_stage(s, sb + s * STAGE); cp_commit(); }

    uint32_t comp_off = 0;
    uint32_t load_off = (NSTAGE - 1) * STAGE;

    for (int i = 0; i < NC; i++) {
        cp_wait1();
        __syncthreads();
        if (i + NSTAGE - 1 < NC) load_stage(i + NSTAGE - 1, sb + load_off);
        cp_commit();
        load_off += STAGE; if (load_off == NSTAGE * STAGE) load_off = 0;

        const uint32_t sA = sb + comp_off, sB = sA + 16384;
        comp_off += STAGE; if (comp_off == NSTAGE * STAGE) comp_off = 0;

#pragma unroll
        for (int kk = 0; kk < 4; kk++) {       // 4 x k16 per BKC=64
            uint32_t ah[4][4], bh[4][4];
            const int ac = kk * 2 + ahalf;
            const int bc = kk * 2 + bhalf;
#pragma unroll
            for (int mi = 0; mi < 4; mi++) {
                const int r = ar + mi * 16;
                ldsm_x4(ah[mi][0], ah[mi][1], ah[mi][2], ah[mi][3],
                        sA + r * 128 + ((ac ^ arx) << 4));
            }
#pragma unroll
            for (int nj = 0; nj < 4; nj++) {
                const int r = br + nj * 16;
                ldsm_x4(bh[nj][0], bh[nj][1], bh[nj][2], bh[nj][3],
                        sB + r * 128 + ((bc ^ brx) << 4));
            }
#pragma unroll
            for (int mi = 0; mi < 4; mi++)
#pragma unroll
                for (int jj = 0; jj < 8; jj++)
                    mma16816(acc[mi][jj], ah[mi], bh[jj >> 1][(jj & 1) * 2], bh[jj >> 1][(jj & 1) * 2 + 1]);
        }
    }
    cp_wait0();

    // ---- epilogue ----
    const int bm_ = blockIdx.y * BM, bn_ = blockIdx.x * BN;
    const float bsc = L2E ? __ldg(betap) : 0.f;

    float* sbuf = (float*)smem;               // 256 floats: [0,128) sums, [128,256) sumsq
    if (STATS) {
        __syncthreads();                       // all warps done reading stage smem
        sbuf[tid] = 0.f;
        sbuf[tid + 128] = 0.f;
        __syncthreads();
    }

#pragma unroll
    for (int jj = 0; jj < 8; jj++) {
        const int coll = wn + jj * 8 + 2 * (lane & 3);   // col within tile
        const int col  = bn_ + coll;
        const float bb0 = __ldg(&bias[col]), bb1 = __ldg(&bias[col + 1]);
        float s0 = 0.f, s1 = 0.f, q0 = 0.f, q1 = 0.f;
#pragma unroll
        for (int mi = 0; mi < 4; mi++) {
            const int row0 = bm_ + wm + mi * 16 + (lane >> 2);
#pragma unroll
            for (int h = 0; h < 2; h++) {
                const int row = row0 + h * 8;
                float v0 = acc[mi][jj][h * 2 + 0] + bb0;
                float v1 = acc[mi][jj][h * 2 + 1] + bb1;
                if (!L2E) {
                    v0 = fmaxf(v0, 0.f); v1 = fmaxf(v1, 0.f);
                    __half2 hv = __halves2half2(__float2half(v0), __float2half(v1));
                    *(__half2*)(Ch + (size_t)row * Nout + col) = hv;
                    if (STATS) {
                        s0 += v0; q0 = fmaf(v0, v0, q0);
                        s1 += v1; q1 = fmaf(v1, v1, q1);
                    }
                } else {
                    const float2 yv = *(const float2*)(Y + (size_t)row * Nout + col);
                    float2 o;
                    o.x = v0 + bsc * yv.x;
                    o.y = v1 + bsc * yv.y;
                    *(float2*)(Cout + (size_t)row * Nout + col) = o;
                }
            }
        }
        if (STATS) {
            // reduce over the 8 lanes sharing this column pair (xor 4/8/16)
#pragma unroll
            for (int m = 4; m <= 16; m <<= 1) {
                s0 += __shfl_xor_sync(0xFFFFFFFF, s0, m);
                s1 += __shfl_xor_sync(0xFFFFFFFF, s1, m);
                q0 += __shfl_xor_sync(0xFFFFFFFF, q0, m);
                q1 += __shfl_xor_sync(0xFFFFFFFF, q1, m);
            }
            if (lane < 4) {
                atomicAdd(&sbuf[coll],           s0);
                atomicAdd(&sbuf[coll + 1],       s1);
                atomicAdd(&sbuf[128 + coll],     q0);
                atomicAdd(&sbuf[128 + coll + 1], q1);
            }
        }
    }

    if (STATS) {
        __syncthreads();
        const size_t pb = (size_t)blockIdx.y * Nout + bn_ + tid;
        g_psum[pb]   = sbuf[tid];
        g_psumsq[pb] = sbuf[128 + tid];
    }
}

// ---------------- launch ----------------
extern "C" void kernel_launch(void* const* d_in, const int* in_sizes, int n_in,
                              void* d_out, int out_size) {
    const float* x    = (const float*)d_in[0];
    const float* y    = (const float*)d_in[1];
    const float* W1   = (const float*)d_in[2];
    const float* b1   = (const float*)d_in[3];
    const float* W2   = (const float*)d_in[4];
    const float* b2   = (const float*)d_in[5];
    const float* bn1g = (const float*)d_in[6];
    const float* bn1b = (const float*)d_in[7];
    const float* bn2g = (const float*)d_in[8];
    const float* bn2b = (const float*)d_in[9];
    const float* beta = (const float*)d_in[10];
    float* out = (float*)d_out;

    __half *xh, *h1, *w1h, *w2h;
    float *b1f, *b2f, *sc1, *sh1, *sc2, *sh2;
    cudaGetSymbolAddress((void**)&xh,  g_xh);
    cudaGetSymbolAddress((void**)&h1,  g_h1);
    cudaGetSymbolAddress((void**)&w1h, g_w1h);
    cudaGetSymbolAddress((void**)&w2h, g_w2h);
    cudaGetSymbolAddress((void**)&b1f, g_b1f);
    cudaGetSymbolAddress((void**)&b2f, g_b2f);
    cudaGetSymbolAddress((void**)&sc1, g_scale1);
    cudaGetSymbolAddress((void**)&sh1, g_shift1);
    cudaGetSymbolAddress((void**)&sc2, g_scale2);
    cudaGetSymbolAddress((void**)&sh2, g_shift2);

    cudaFuncSetAttribute(gemm_mma<false, true>, cudaFuncAttributeMaxDynamicSharedMemorySize, SMEM_DYN);
    cudaFuncSetAttribute(gemm_mma<true, false>, cudaFuncAttributeMaxDynamicSharedMemorySize, SMEM_DYN);

    // layer 1 (GEMM1 epilogue emits h1 column-stat partials; by-grid = RSX = 256)
    conv_stats_x<<<dim3(NFEAT / 1024, RSX), 256>>>(x, xh, NFEAT, NROWS / RSX);
    col_stats_finalize<<<NFEAT / 256, 256>>>(bn1g, bn1b, sc1, sh1, NFEAT);
    fold_split<<<NHID, 256>>>(W1, b1, sc1, sh1, w1h, b1f, NFEAT);
    gemm_mma<false, true><<<dim3(NHID / BN, NROWS / BM), 128, SMEM_DYN>>>(
        xh, w1h, b1f, nullptr, nullptr, nullptr, h1, NFEAT, NHID);

    // layer 2 (stats pass eliminated — partials came from GEMM1)
    col_stats_finalize<<<NHID / 256, 256>>>(bn2g, bn2b, sc2, sh2, NHID);
    fold_split<<<NCLS, 256>>>(W2, b2, sc2, sh2, w2h, b2f, NHID);
    gemm_mma<true, false><<<dim3(NCLS / BN, NROWS / BM), 128, SMEM_DYN>>>(
        h1, w2h, b2f, y, beta, out, nullptr, NHID, NCLS);
}

// round 14
// speedup vs baseline: 1.1764x; 1.1764x over previous
#include <cuda_runtime.h>
#include <cuda_fp16.h>
#include <cstdint>

#define NROWS 32768
#define NFEAT 2048
#define NHID  4096
#define NCLS  512
#define RSX   256            // partial-split factor for column stats

// GEMM tiling: 128x128 CTA tile, BKC=64, 4 warps (2x2), warp tile 64x64
#define BM 128
#define BN 128
#define BKC 64
#define STAGE 32768          // A 16K + B 16K (128B rows, SW128 swizzle)
#define NSTAGE 3
#define SMEM_DYN (NSTAGE * STAGE)

// ---------------- device scratch ----------------
__device__ __half g_xh [(size_t)NROWS * NFEAT];
__device__ __half g_h1 [(size_t)NROWS * NHID];
__device__ __half g_w1h[(size_t)NHID  * NFEAT];
__device__ __half g_w2h[(size_t)NCLS  * NHID];
__device__ float  g_b1f[NHID];
__device__ float  g_b2f[NCLS];
__device__ float  g_scale1[NFEAT], g_shift1[NFEAT];
__device__ float  g_scale2[NHID],  g_shift2[NHID];
__device__ float  g_psum  [(size_t)RSX * NHID];
__device__ float  g_psumsq[(size_t)RSX * NHID];

// ---------------- PTX helpers (family-portable only: sm_80-era) ----------------
__device__ __forceinline__ uint32_t smem_u32(const void* p) {
    uint32_t a;
    asm("{ .reg .u64 t; cvta.to.shared.u64 t, %1; cvt.u32.u64 %0, t; }" : "=r"(a) : "l"(p));
    return a;
}
__device__ __forceinline__ void cp16(uint32_t s, const void* g) {
    asm volatile("cp.async.cg.shared.global [%0], [%1], 16;" :: "r"(s), "l"(g));
}
__device__ __forceinline__ void cp_commit() { asm volatile("cp.async.commit_group;" ::: "memory"); }
__device__ __forceinline__ void cp_wait1()  { asm volatile("cp.async.wait_group 1;" ::: "memory"); }
__device__ __forceinline__ void cp_wait0()  { asm volatile("cp.async.wait_group 0;" ::: "memory"); }

__device__ __forceinline__ void ldsm_x4(uint32_t& d0, uint32_t& d1, uint32_t& d2, uint32_t& d3, uint32_t addr) {
    asm volatile("ldmatrix.sync.aligned.m8n8.x4.shared.b16 {%0,%1,%2,%3}, [%4];"
                 : "=r"(d0), "=r"(d1), "=r"(d2), "=r"(d3) : "r"(addr));
}
__device__ __forceinline__ void mma16816(float* c, const uint32_t* a, uint32_t b0, uint32_t b1) {
    asm volatile("mma.sync.aligned.m16n8k16.row.col.f32.f16.f16.f32 "
                 "{%0,%1,%2,%3}, {%4,%5,%6,%7}, {%8,%9}, {%0,%1,%2,%3};"
                 : "+f"(c[0]), "+f"(c[1]), "+f"(c[2]), "+f"(c[3])
                 : "r"(a[0]), "r"(a[1]), "r"(a[2]), "r"(a[3]), "r"(b0), "r"(b1));
}

// ---------------- stats / conversion kernels (fp32 partials, wide grids) ----------------
// grid (C/1024, RSX); each thread owns 4 consecutive columns over 128 rows.
__global__ __launch_bounds__(256)
void conv_stats_x(const float* __restrict__ X, __half* __restrict__ Xh,
                  int C, int rowsPer) {
    const int c4 = (blockIdx.x * 256 + threadIdx.x) * 4;
    const size_t base = (size_t)blockIdx.y * rowsPer * C + c4;
    float s0 = 0, s1 = 0, s2 = 0, s3 = 0;
    float q0 = 0, q1 = 0, q2 = 0, q3 = 0;
    for (int r = 0; r < rowsPer; r += 4) {
#pragma unroll
        for (int u = 0; u < 4; u++) {
            const size_t o = base + (size_t)(r + u) * C;
            float4 v = *(const float4*)(X + o);
            s0 += v.x; q0 = fmaf(v.x, v.x, q0);
            s1 += v.y; q1 = fmaf(v.y, v.y, q1);
            s2 += v.z; q2 = fmaf(v.z, v.z, q2);
            s3 += v.w; q3 = fmaf(v.w, v.w, q3);
            __half2 hA = __halves2half2(__float2half(v.x), __float2half(v.y));
            __half2 hB = __halves2half2(__float2half(v.z), __float2half(v.w));
            *(uint2*)(Xh + o) = make_uint2(*(uint32_t*)&hA, *(uint32_t*)&hB);
        }
    }
    const int pb = blockIdx.y * C + c4;
    g_psum[pb + 0] = s0; g_psum[pb + 1] = s1; g_psum[pb + 2] = s2; g_psum[pb + 3] = s3;
    g_psumsq[pb + 0] = q0; g_psumsq[pb + 1] = q1; g_psumsq[pb + 2] = q2; g_psumsq[pb + 3] = q3;
}

__global__ void col_stats_finalize(const float* __restrict__ gamma, const float* __restrict__ bnb,
                                   float* __restrict__ scale, float* __restrict__ shift, int C) {
    int c = blockIdx.x * 256 + threadIdx.x;
    double s = 0, q = 0;
    for (int i = 0; i < RSX; i++) { s += (double)g_psum[(size_t)i * C + c]; q += (double)g_psumsq[(size_t)i * C + c]; }
    double mu  = s * (1.0 / NROWS);
    double var = q * (1.0 / NROWS) - mu * mu;
    float a = rsqrtf((float)var + 1e-5f) * gamma[c];
    scale[c] = a;
    shift[c] = bnb[c] - (float)mu * a;
}

__global__ void fold_split(const float* __restrict__ W, const float* __restrict__ bias,
                           const float* __restrict__ scale, const float* __restrict__ shift,
                           __half* __restrict__ Wh, float* __restrict__ bf, int K) {
    int j = blockIdx.x;
    const float* Wr = W + (size_t)j * K;
    float dot = 0.f;
    for (int k = threadIdx.x; k < K; k += 256) {
        float w = Wr[k];
        Wh[(size_t)j * K + k] = __float2half(w * scale[k]);
        dot += w * shift[k];
    }
    __shared__ float red[256];
    red[threadIdx.x] = dot;
    __syncthreads();
    for (int s = 128; s > 0; s >>= 1) {
        if (threadIdx.x < s) red[threadIdx.x] += red[threadIdx.x + s];
        __syncthreads();
    }
    if (threadIdx.x == 0) bf[j] = bias[j] + red[0];
}

// ---------------- mma.sync GEMM: C = A[M,K] @ B[N,K]^T  (fp16, warp tile 64x64) -----------
// 128 threads (4 warps, 2x2), double-buffered fragment pipeline (ldsm prefetch).
// STATS: fused h1 column-stat partials (layer-1 path).
template <bool L2E, bool STATS>
__global__ __launch_bounds__(128, 2)
void gemm_mma(const __half* __restrict__ A, const __half* __restrict__ B,
              const float* __restrict__ bias, const float* __restrict__ Y,
              const float* __restrict__ betap, float* __restrict__ Cout,
              __half* __restrict__ Ch, int K, int Nout) {
    extern __shared__ __align__(1024) char smem[];
    const uint32_t sb = smem_u32(smem);
    const int tid  = threadIdx.x;
    const int wid  = tid >> 5;
    const int lane = tid & 31;
    const int wm   = (wid >> 1) * 64;      // warp m offset in tile
    const int wn   = (wid & 1) * 64;       // warp n offset in tile

    const int ldb = K * 2;  // row stride, bytes
    const char* gA = (const char*)(A + (size_t)(blockIdx.y * BM) * K);
    const char* gB = (const char*)(B + (size_t)(blockIdx.x * BN) * K);
    const int NC = K / BKC;

    // loader: per stage, A = 128x128B + B same; 8 chunks each per thread (128 threads)
    const int lr = tid >> 3;          // 0..15
    const int lc = tid & 7;           // chunk col 0..7
    auto load_stage = [&](int ch, uint32_t s0) {
        size_t kb = (size_t)ch * 128; // 64 halves = 128 bytes
#pragma unroll
        for (int t = 0; t < 8; t++) {
            int r = lr + t * 16;
            uint32_t so = (uint32_t)r * 128 + (uint32_t)((lc ^ (r & 7)) << 4);
            size_t go = (size_t)r * ldb + kb + lc * 16;
            cp16(s0 + so,         gA + go);
            cp16(s0 + 16384 + so, gB + go);
        }
    };

    float acc[4][8][4];
#pragma unroll
    for (int i = 0; i < 4; i++)
#pragma unroll
        for (int j = 0; j < 8; j++)
#pragma unroll
            for (int r = 0; r < 4; r++) acc[i][j][r] = 0.f;

    // hoisted fragment row bases (per-warp invariant)
    const int ar  = wm + (lane & 15);
    const int arx = ar & 7;
    const int br  = wn + (lane & 7) + ((lane & 16) ? 8 : 0);
    const int brx = br & 7;
    const int ahalf = (lane >> 4);
    const int bhalf = ((lane >> 3) & 1);

    // double-buffered fragments
    uint32_t ah[2][4][4], bh[2][4][4];
    auto load_frags = [&](uint32_t sA, uint32_t sB, int kk, int buf) {
        const int ac = kk * 2 + ahalf;
        const int bc = kk * 2 + bhalf;
#pragma unroll
        for (int mi = 0; mi < 4; mi++) {
            const int r = ar + mi * 16;
            ldsm_x4(ah[buf][mi][0], ah[buf][mi][1], ah[buf][mi][2], ah[buf][mi][3],
                    sA + r * 128 + ((ac ^ arx) << 4));
        }
#pragma unroll
        for (int nj = 0; nj < 4; nj++) {
            const int r = br + nj * 16;
            ldsm_x4(bh[buf][nj][0], bh[buf][nj][1], bh[buf][nj][2], bh[buf][nj][3],
                    sB + r * 128 + ((bc ^ brx) << 4));
        }
    };
    auto do_mma = [&](int buf) {
#pragma unroll
        for (int mi = 0; mi < 4; mi++)
#pragma unroll
            for (int jj = 0; jj < 8; jj++)
                mma16816(acc[mi][jj], ah[buf][mi],
                         bh[buf][jj >> 1][(jj & 1) * 2], bh[buf][jj >> 1][(jj & 1) * 2 + 1]);
    };

    // prologue: stages 0,1 in flight; frags (0,0) loaded
    load_stage(0, sb);          cp_commit();
    load_stage(1, sb + STAGE);  cp_commit();
    cp_wait1();
    __syncthreads();
    load_frags(sb, sb + 16384, 0, 0);

    uint32_t comp_off = 0;
    uint32_t load_off = 2 * STAGE;
    int cb = 0;

    for (int i = 0; i < NC; i++) {
        // issue loads for stage i+2 (slot released by prev iteration's sync)
        if (i + 2 < NC) load_stage(i + 2, sb + load_off);
        cp_commit();
        load_off += STAGE; if (load_off == NSTAGE * STAGE) load_off = 0;

        const uint32_t cA = sb + comp_off, cB = cA + 16384;
        comp_off += STAGE; if (comp_off == NSTAGE * STAGE) comp_off = 0;

        // kk = 0..2: prefetch kk+1 while computing kk
#pragma unroll
        for (int kk = 0; kk < 3; kk++) {
            load_frags(cA, cB, kk + 1, cb ^ 1);
            do_mma(cb);
            cb ^= 1;
        }
        // stage i+1 ready (commit schedule) + release stage i's smem reads
        cp_wait1();
        __syncthreads();
        if (i + 1 < NC) {
            const uint32_t nA = sb + comp_off, nB = nA + 16384;  // next chunk slot
            load_frags(nA, nB, 0, cb ^ 1);
        }
        do_mma(cb);
        cb ^= 1;
    }
    cp_wait0();

    // ---- epilogue ----
    const int bm_ = blockIdx.y * BM, bn_ = blockIdx.x * BN;
    const float bsc = L2E ? __ldg(betap) : 0.f;

    float* sbuf = (float*)smem;               // 256 floats: [0,128) sums, [128,256) sumsq
    if (STATS) {
        __syncthreads();                       // all warps done with stage smem
        sbuf[tid] = 0.f;
        sbuf[tid + 128] = 0.f;
        __syncthreads();
    }

#pragma unroll
    for (int jj = 0; jj < 8; jj++) {
        const int coll = wn + jj * 8 + 2 * (lane & 3);   // col within tile
        const int col  = bn_ + coll;
        const float bb0 = __ldg(&bias[col]), bb1 = __ldg(&bias[col + 1]);
        float s0 = 0.f, s1 = 0.f, q0 = 0.f, q1 = 0.f;
#pragma unroll
        for (int mi = 0; mi < 4; mi++) {
            const int row0 = bm_ + wm + mi * 16 + (lane >> 2);
#pragma unroll
            for (int h = 0; h < 2; h++) {
                const int row = row0 + h * 8;
                float v0 = acc[mi][jj][h * 2 + 0] + bb0;
                float v1 = acc[mi][jj][h * 2 + 1] + bb1;
                if (!L2E) {
                    v0 = fmaxf(v0, 0.f); v1 = fmaxf(v1, 0.f);
                    __half2 hv = __halves2half2(__float2half(v0), __float2half(v1));
                    *(__half2*)(Ch + (size_t)row * Nout + col) = hv;
                    if (STATS) {
                        s0 += v0; q0 = fmaf(v0, v0, q0);
                        s1 += v1; q1 = fmaf(v1, v1, q1);
                    }
                } else {
                    const float2 yv = *(const float2*)(Y + (size_t)row * Nout + col);
                    float2 o;
                    o.x = v0 + bsc * yv.x;
                    o.y = v1 + bsc * yv.y;
                    *(float2*)(Cout + (size_t)row * Nout + col) = o;
                }
            }
        }
        if (STATS) {
            // reduce over the 8 lanes sharing this column pair (xor 4/8/16)
#pragma unroll
            for (int m = 4; m <= 16; m <<= 1) {
                s0 += __shfl_xor_sync(0xFFFFFFFF, s0, m);
                s1 += __shfl_xor_sync(0xFFFFFFFF, s1, m);
                q0 += __shfl_xor_sync(0xFFFFFFFF, q0, m);
                q1 += __shfl_xor_sync(0xFFFFFFFF, q1, m);
            }
            if (lane < 4) {
                atomicAdd(&sbuf[coll],           s0);
                atomicAdd(&sbuf[coll + 1],       s1);
                atomicAdd(&sbuf[128 + coll],     q0);
                atomicAdd(&sbuf[128 + coll + 1], q1);
            }
        }
    }

    if (STATS) {
        __syncthreads();
        const size_t pb = (size_t)blockIdx.y * Nout + bn_ + tid;
        g_psum[pb]   = sbuf[tid];
        g_psumsq[pb] = sbuf[128 + tid];
    }
}

// ---------------- launch ----------------
extern "C" void kernel_launch(void* const* d_in, const int* in_sizes, int n_in,
                              void* d_out, int out_size) {
    const float* x    = (const float*)d_in[0];
    const float* y    = (const float*)d_in[1];
    const float* W1   = (const float*)d_in[2];
    const float* b1   = (const float*)d_in[3];
    const float* W2   = (const float*)d_in[4];
    const float* b2   = (const float*)d_in[5];
    const float* bn1g = (const float*)d_in[6];
    const float* bn1b = (const float*)d_in[7];
    const float* bn2g = (const float*)d_in[8];
    const float* bn2b = (const float*)d_in[9];
    const float* beta = (const float*)d_in[10];
    float* out = (float*)d_out;

    __half *xh, *h1, *w1h, *w2h;
    float *b1f, *b2f, *sc1, *sh1, *sc2, *sh2;
    cudaGetSymbolAddress((void**)&xh,  g_xh);
    cudaGetSymbolAddress((void**)&h1,  g_h1);
    cudaGetSymbolAddress((void**)&w1h, g_w1h);
    cudaGetSymbolAddress((void**)&w2h, g_w2h);
    cudaGetSymbolAddress((void**)&b1f, g_b1f);
    cudaGetSymbolAddress((void**)&b2f, g_b2f);
    cudaGetSymbolAddress((void**)&sc1, g_scale1);
    cudaGetSymbolAddress((void**)&sh1, g_shift1);
    cudaGetSymbolAddress((void**)&sc2, g_scale2);
    cudaGetSymbolAddress((void**)&sh2, g_shift2);

    cudaFuncSetAttribute(gemm_mma<false, true>, cudaFuncAttributeMaxDynamicSharedMemorySize, SMEM_DYN);
    cudaFuncSetAttribute(gemm_mma<true, false>, cudaFuncAttributeMaxDynamicSharedMemorySize, SMEM_DYN);

    // layer 1 (GEMM1 epilogue emits h1 column-stat partials; by-grid = RSX = 256)
    conv_stats_x<<<dim3(NFEAT / 1024, RSX), 256>>>(x, xh, NFEAT, NROWS / RSX);
    col_stats_finalize<<<NFEAT / 256, 256>>>(bn1g, bn1b, sc1, sh1, NFEAT);
    fold_split<<<NHID, 256>>>(W1, b1, sc1, sh1, w1h, b1f, NFEAT);
    gemm_mma<false, true><<<dim3(NHID / BN, NROWS / BM), 128, SMEM_DYN>>>(
        xh, w1h, b1f, nullptr, nullptr, nullptr, h1, NFEAT, NHID);

    // layer 2 (stats pass eliminated — partials came from GEMM1)
    col_stats_finalize<<<NHID / 256, 256>>>(bn2g, bn2b, sc2, sh2, NHID);
    fold_split<<<NCLS, 256>>>(W2, b2, sc2, sh2, w2h, b2f, NHID);
    gemm_mma<true, false><<<dim3(NCLS / BN, NROWS / BM), 128, SMEM_DYN>>>(
        h1, w2h, b2f, y, beta, out, nullptr, NHID, NCLS);
}